// round 7
// baseline (speedup 1.0000x reference)
#include <cuda_runtime.h>
#include <cuda_bf16.h>
#include <mma.h>
#include <cstdint>
#include <cstddef>

using namespace nvcuda;
typedef __nv_bfloat16 bf16;

#define S_TOTAL     5120
#define EPSLN       1e-5f
#define BATCH_ELEMS 327680

// ===================== scratch (static __device__) ==========================
__device__ float g_qk  [S_TOTAL * 1024];
__device__ float g_att [S_TOTAL * 256];
__device__ float g_out1[S_TOTAL * 256];
__device__ float g_y   [S_TOTAL * 256];

__device__ bf16 g_xc_h[S_TOTAL * 256],  g_xc_l[S_TOTAL * 256];
__device__ bf16 g_xb_h[S_TOTAL * 1024], g_xb_l[S_TOTAL * 1024];
__device__ bf16 g_o1_h[S_TOTAL * 256],  g_o1_l[S_TOTAL * 256];
__device__ bf16 g_h1_h[S_TOTAL * 1024], g_h1_l[S_TOTAL * 1024];

__device__ bf16 g_Mt_h[262144], g_Mt_l[262144];   // (1024, 256)  qk weights
__device__ bf16 g_Pt_h[262144], g_Pt_l[262144];   // (256, 1024)  att weights
__device__ bf16 g_W1_h[262144], g_W1_l[262144];
__device__ bf16 g_W2_h[262144], g_W2_l[262144];
__device__ float g_c1[1024];
__device__ float g_c2[256];

__device__ float2 g_part[160];
__device__ float g_mu[4];
__device__ float g_rsd[4];

// ===================== helpers ==============================================
__device__ __forceinline__ void split_store(float v, bf16* hi, bf16* lo, size_t i) {
    bf16 h = __float2bfloat16(v);
    hi[i] = h;
    lo[i] = __float2bfloat16(v - __bfloat162float(h));
}
__device__ __forceinline__ uint32_t smem_u32(const void* p) {
    uint32_t a;
    asm("{ .reg .u64 t; cvta.to.shared.u64 t, %1; cvt.u32.u64 %0, t; }" : "=r"(a) : "l"(p));
    return a;
}
__device__ __forceinline__ void cp16(void* dst, const void* src) {
    asm volatile("cp.async.cg.shared.global [%0], [%1], 16;" ::
                 "r"(smem_u32(dst)), "l"(src));
}
#define CP_COMMIT()  asm volatile("cp.async.commit_group;" ::: "memory")
#define CP_WAIT(n)   asm volatile("cp.async.wait_group %0;" :: "n"(n) : "memory")

// ===================== weight precompute ====================================
// Mt[n=h*256+fo][fi] = 0.125 * sum_d Wq[(h*64+d)*256+fi] * Wk[(h*64+d)*256+fo]
// c1[n]            = 0.125 * sum_d bq[h*64+d] * Wk[(h*64+d)*256+fo]
__global__ void mt_kernel(const float* __restrict__ Wq, const float* __restrict__ bq,
                          const float* __restrict__ Wk) {
    __shared__ float wk_s[64];
    const int n = blockIdx.x, h = n >> 8, fo = n & 255;
    const int tid = threadIdx.x;
    if (tid < 64) wk_s[tid] = Wk[(h * 64 + tid) * 256 + fo];
    __syncthreads();
    float acc = 0.f;
#pragma unroll 8
    for (int d = 0; d < 64; d++)
        acc += Wq[(h * 64 + d) * 256 + tid] * wk_s[d];
    split_store(0.125f * acc, g_Mt_h, g_Mt_l, (size_t)n * 256 + tid);
    if (tid == 0) {
        float c = 0.f;
        for (int d = 0; d < 64; d++) c += bq[h * 64 + d] * wk_s[d];
        g_c1[n] = 0.125f * c;
    }
}

// Pt[o][h*256+f] = sum_d Wv[(h*64+d)*256+f] * Wf[o*256 + h*64+d]
__global__ void pt_kernel(const float* __restrict__ Wv, const float* __restrict__ Wf) {
    __shared__ float wf_s[1024];
    const int o = blockIdx.x, tid = threadIdx.x;
#pragma unroll
    for (int j = 0; j < 4; j++) wf_s[j * 256 + tid] = Wf[o * 256 + j * 256 + tid];
    __syncthreads();
#pragma unroll
    for (int h = 0; h < 4; h++) {
        float acc = 0.f;
#pragma unroll 8
        for (int d = 0; d < 64; d++)
            acc += Wv[(h * 64 + d) * 256 + tid] * wf_s[h * 64 + d];
        split_store(acc, g_Pt_h, g_Pt_l, (size_t)o * 1024 + h * 256 + tid);
    }
}

// c2[o] = sum_hd bv[hd]*Wf[o*256+hd] + bf[o]
__global__ void c2_kernel(const float* __restrict__ bv, const float* __restrict__ Wf,
                          const float* __restrict__ bff) {
    __shared__ float bv_s[256];
    const int o = threadIdx.x;
    bv_s[o] = bv[o];
    __syncthreads();
    float acc = bff[o];
    for (int j = 0; j < 256; j++) acc += bv_s[j] * Wf[o * 256 + j];
    g_c2[o] = acc;
}

// W1 + W2 split in one launch (524288 elems)
__global__ void w12_cvt_kernel(const float* __restrict__ W1, const float* __restrict__ W2) {
    int i = blockIdx.x * 256 + threadIdx.x;
    if (i < 262144) split_store(W1[i], g_W1_h, g_W1_l, i);
    else            split_store(W2[i - 262144], g_W2_h, g_W2_l, i - 262144);
}

// gather patch-center rows of x
__global__ void center_cvt_kernel(const float* __restrict__ x) {
    int s = blockIdx.x, f = threadIdx.x;
    split_store(x[(size_t)s * 6400 + 3072 + f], g_xc_h, g_xc_l, (size_t)s * 256 + f);
}

// ===================== pipelined wmma split-bf16 GEMM =======================
// C[m,n] = sum_k A[m,k]*B[n,k];  BM=128, BN=64, BK=32, 256 thr, 3-stage cp.async
#define LDT 40
#define ST_A_H 0
#define ST_A_L (128 * LDT)
#define ST_B_H (256 * LDT)
#define ST_B_L (320 * LDT)
#define STAGE_ELEMS (384 * LDT)           // 384 rows x LDT bf16 = 30720 B
#define MM_SMEM (3 * STAGE_ELEMS * 2)     // 92160 B dynamic smem

template<bool RELU, bool BIAS, bool RES, bool WF32, bool WBF16, bool STATS>
__global__ __launch_bounds__(256) void mm_kernel(
    const bf16* __restrict__ Ahi, const bf16* __restrict__ Alo, int lda,
    const bf16* __restrict__ Bhi, const bf16* __restrict__ Blo, int ldb,
    float* __restrict__ Cf, bf16* __restrict__ Chi, bf16* __restrict__ Clo, int ldc,
    const float* __restrict__ bias,
    const float* __restrict__ Res, int ldr, int Ktot)
{
    extern __shared__ __align__(16) char dynsm[];
    bf16* stg = (bf16*)dynsm;
    float* cout = (float*)dynsm;          // aliased after pipeline drain
    __shared__ float rbuf[512];

    const int tid = threadIdx.x;
    const int wid = tid >> 5;
    const int wm = wid >> 1, wn = wid & 1;
    const int m0 = blockIdx.y * 128, n0 = blockIdx.x * 64;

    // loader mapping
    const int ar0 = tid >> 2,         ac0 = (tid & 3) * 8;
    const int ar1 = (tid + 256) >> 2, ac1 = (tid & 3) * 8;
    const int br  = tid >> 2,         bc  = (tid & 3) * 8;

    const int KT = Ktot >> 5;

    auto issue = [&](int s, int kt) {
        bf16* st = stg + s * STAGE_ELEMS;
        const int k0 = kt << 5;
        cp16(st + ST_A_H + ar0 * LDT + ac0, Ahi + (size_t)(m0 + ar0) * lda + k0 + ac0);
        cp16(st + ST_A_L + ar0 * LDT + ac0, Alo + (size_t)(m0 + ar0) * lda + k0 + ac0);
        cp16(st + ST_A_H + ar1 * LDT + ac1, Ahi + (size_t)(m0 + ar1) * lda + k0 + ac1);
        cp16(st + ST_A_L + ar1 * LDT + ac1, Alo + (size_t)(m0 + ar1) * lda + k0 + ac1);
        cp16(st + ST_B_H + br * LDT + bc,   Bhi + (size_t)(n0 + br) * ldb + k0 + bc);
        cp16(st + ST_B_L + br * LDT + bc,   Blo + (size_t)(n0 + br) * ldb + k0 + bc);
    };

    wmma::fragment<wmma::accumulator, 16, 16, 16, float> cacc[2][2];
#pragma unroll
    for (int i = 0; i < 2; i++)
#pragma unroll
        for (int j = 0; j < 2; j++) wmma::fill_fragment(cacc[i][j], 0.0f);

    // prologue: 2 stages in flight
    issue(0, 0); CP_COMMIT();
    issue(1, 1); CP_COMMIT();

    for (int kt = 0; kt < KT; kt++) {
        CP_WAIT(1);
        __syncthreads();
        const bf16* st = stg + (kt % 3) * STAGE_ELEMS;
#pragma unroll
        for (int ks = 0; ks < 32; ks += 16) {
            wmma::fragment<wmma::matrix_a, 16, 16, 16, bf16, wmma::row_major> ah[2], al[2];
            wmma::fragment<wmma::matrix_b, 16, 16, 16, bf16, wmma::col_major> bh[2], bl[2];
#pragma unroll
            for (int i = 0; i < 2; i++) {
                const int row = wm * 32 + i * 16;
                wmma::load_matrix_sync(ah[i], st + ST_A_H + row * LDT + ks, LDT);
                wmma::load_matrix_sync(al[i], st + ST_A_L + row * LDT + ks, LDT);
            }
#pragma unroll
            for (int j = 0; j < 2; j++) {
                const int col = wn * 32 + j * 16;
                wmma::load_matrix_sync(bh[j], st + ST_B_H + col * LDT + ks, LDT);
                wmma::load_matrix_sync(bl[j], st + ST_B_L + col * LDT + ks, LDT);
            }
#pragma unroll
            for (int i = 0; i < 2; i++)
#pragma unroll
                for (int j = 0; j < 2; j++) {
                    wmma::mma_sync(cacc[i][j], ah[i], bh[j], cacc[i][j]);
                    wmma::mma_sync(cacc[i][j], ah[i], bl[j], cacc[i][j]);
                    wmma::mma_sync(cacc[i][j], al[i], bh[j], cacc[i][j]);
                }
        }
        __syncthreads();
        if (kt + 2 < KT) issue((kt + 2) % 3, kt + 2);
        CP_COMMIT();
    }
    CP_WAIT(0);
    __syncthreads();

    // stage accumulators through SMEM (aliases stage buffers)
#pragma unroll
    for (int i = 0; i < 2; i++)
#pragma unroll
        for (int j = 0; j < 2; j++)
            wmma::store_matrix_sync(
                cout + (wm * 32 + i * 16) * 64 + wn * 32 + j * 16,
                cacc[i][j], 64, wmma::mem_row_major);
    __syncthreads();

    // postprocess: one half-row of 32 floats per thread
    const int r = tid >> 1, ch = (tid & 1) * 32;
    const int m = m0 + r;
    float* cf = nullptr; bf16* chi = nullptr; bf16* clo = nullptr;
    if (WF32)  cf  = Cf  + (size_t)m * ldc + n0 + ch;
    if (WBF16) { chi = Chi + (size_t)m * ldc + n0 + ch;
                 clo = Clo + (size_t)m * ldc + n0 + ch; }

    float lsum = 0.f, lss = 0.f;
#pragma unroll
    for (int q = 0; q < 8; q++) {
        float4 v = *(float4*)(cout + r * 64 + ch + q * 4);
        if (BIAS) {
            const float4 b4 = *(const float4*)(bias + n0 + ch + q * 4);
            v.x += b4.x; v.y += b4.y; v.z += b4.z; v.w += b4.w;
        }
        if (RELU) {
            v.x = fmaxf(v.x, 0.f); v.y = fmaxf(v.y, 0.f);
            v.z = fmaxf(v.z, 0.f); v.w = fmaxf(v.w, 0.f);
        }
        if (RES) {
            const float4 r4 = *(const float4*)(Res + (size_t)m * ldr + n0 + ch + q * 4);
            v.x += r4.x; v.y += r4.y; v.z += r4.z; v.w += r4.w;
        }
        if (STATS) {
            lsum += v.x + v.y + v.z + v.w;
            lss  += v.x * v.x + v.y * v.y + v.z * v.z + v.w * v.w;
        }
        if (WF32) *(float4*)(cf + q * 4) = v;
        if (WBF16) {
            float vv[4] = {v.x, v.y, v.z, v.w};
#pragma unroll
            for (int j = 0; j < 4; j += 2) {
                bf16 h0 = __float2bfloat16(vv[j]);
                bf16 h1 = __float2bfloat16(vv[j + 1]);
                __nv_bfloat162 hp; hp.x = h0; hp.y = h1;
                __nv_bfloat162 lp;
                lp.x = __float2bfloat16(vv[j]     - __bfloat162float(h0));
                lp.y = __float2bfloat16(vv[j + 1] - __bfloat162float(h1));
                *(__nv_bfloat162*)(chi + q * 4 + j) = hp;
                *(__nv_bfloat162*)(clo + q * 4 + j) = lp;
            }
        }
    }

    if (STATS) {
        rbuf[tid] = lsum; rbuf[256 + tid] = lss;
        __syncthreads();
        for (int o = 128; o; o >>= 1) {
            if (tid < o) {
                rbuf[tid] += rbuf[tid + o];
                rbuf[256 + tid] += rbuf[256 + tid + o];
            }
            __syncthreads();
        }
        if (tid == 0)
            g_part[blockIdx.y * gridDim.x + blockIdx.x] = make_float2(rbuf[0], rbuf[256]);
    }
}

// ===================== fused attention (fp32, memory-bound) =================
__global__ void attn_kernel(const float* __restrict__ x,
                            const float* __restrict__ qk) {
    __shared__ float xs[6400];
    __shared__ float qs[1024];
    __shared__ float scr[128];
    __shared__ float wts[128];

    const int s = blockIdx.x;
    const int tid = threadIdx.x;

    const float4* xg = (const float4*)(x + (size_t)s * 6400);
    for (int i = tid; i < 1600; i += 256) ((float4*)xs)[i] = xg[i];
    ((float4*)qs)[tid] = ((const float4*)(qk + (size_t)s * 1024))[tid];
    __syncthreads();

    const int w = tid >> 5, l = tid & 31;
    for (int d = w; d < 100; d += 8) {
        const int h = d / 25, p = d % 25;
        const float* xp = xs + p * 256;
        const float* qh = qs + h * 256;
        float acc = 0.f;
#pragma unroll
        for (int f = l; f < 256; f += 32) acc += qh[f] * xp[f];
#pragma unroll
        for (int o = 16; o; o >>= 1) acc += __shfl_xor_sync(0xffffffffu, acc, o);
        if (l == 0) scr[d] = acc;              // 1/8 folded into Mt/c1
    }
    __syncthreads();

    if (tid < 4) {
        float mx = -1e30f;
        for (int p = 0; p < 25; p++) mx = fmaxf(mx, scr[tid * 25 + p]);
        float e[25], sum = 0.f;
        for (int p = 0; p < 25; p++) { e[p] = expf(scr[tid * 25 + p] - mx); sum += e[p]; }
        const float inv = 1.f / sum;
        for (int p = 0; p < 25; p++) wts[tid * 25 + p] = e[p] * inv;
    }
    __syncthreads();

    float acc[4] = {0.f, 0.f, 0.f, 0.f};
    for (int p = 0; p < 25; p++) {
        const float v = xs[p * 256 + tid];
#pragma unroll
        for (int h = 0; h < 4; h++) acc[h] += wts[h * 25 + p] * v;
    }
#pragma unroll
    for (int h = 0; h < 4; h++)
        split_store(acc[h], g_xb_h, g_xb_l, (size_t)s * 1024 + h * 256 + tid);
}

// ===================== LayerNorm finalize + apply ===========================
__global__ void finalize_kernel() {
    const int b = threadIdx.x;
    if (b < 4) {
        float s = 0.f, ss = 0.f;
        for (int y = b * 10; y < b * 10 + 10; y++)
            for (int xg = 0; xg < 4; xg++) {
                const float2 v = g_part[y * 4 + xg];
                s += v.x; ss += v.y;
            }
        const float mu = s / (float)BATCH_ELEMS;
        const float var = ss / (float)BATCH_ELEMS - mu * mu;
        g_mu[b] = mu;
        g_rsd[b] = rsqrtf(var + EPSLN);
    }
}

__global__ void ln_apply_kernel(const float* __restrict__ src,
                                const float* __restrict__ w,
                                const float* __restrict__ bb,
                                float* __restrict__ dst,
                                bf16* __restrict__ dhi, bf16* __restrict__ dlo) {
    const int i = blockIdx.x * 256 + threadIdx.x;
    const int b = i / BATCH_ELEMS;
    const int r = i - b * BATCH_ELEMS;
    const float v = (src[i] - g_mu[b]) * g_rsd[b] * w[r] + bb[r];
    dst[i] = v;
    if (dhi) split_store(v, dhi, dlo, i);
}

// ===================== launch ===============================================
#define SYM(T, p, s) T* p; { void* t_; cudaGetSymbolAddress(&t_, s); p = (T*)t_; }

extern "C" void kernel_launch(void* const* d_in, const int* in_sizes, int n_in,
                              void* d_out, int out_size) {
    const float* x    = (const float*)d_in[0];
    const float* Wq   = (const float*)d_in[1];
    const float* bq   = (const float*)d_in[2];
    const float* Wk   = (const float*)d_in[3];
    // bk (d_in[4]) irrelevant: constant shift under softmax
    const float* Wv   = (const float*)d_in[5];
    const float* bv   = (const float*)d_in[6];
    const float* Wf   = (const float*)d_in[7];
    const float* bf_  = (const float*)d_in[8];
    const float* ln1w = (const float*)d_in[9];
    const float* ln1b = (const float*)d_in[10];
    const float* ln2w = (const float*)d_in[11];
    const float* ln2b = (const float*)d_in[12];
    const float* W1   = (const float*)d_in[13];
    const float* b1   = (const float*)d_in[14];
    const float* W2   = (const float*)d_in[15];
    const float* b2   = (const float*)d_in[16];
    float* out = (float*)d_out;

    SYM(float, qkp,  g_qk);   SYM(float, attp, g_att);
    SYM(float, o1p,  g_out1); SYM(float, yp,   g_y);
    SYM(bf16, xch, g_xc_h);   SYM(bf16, xcl, g_xc_l);
    SYM(bf16, xbh, g_xb_h);   SYM(bf16, xbl, g_xb_l);
    SYM(bf16, o1h, g_o1_h);   SYM(bf16, o1l, g_o1_l);
    SYM(bf16, h1h, g_h1_h);   SYM(bf16, h1l, g_h1_l);
    SYM(bf16, mth, g_Mt_h);   SYM(bf16, mtl, g_Mt_l);
    SYM(bf16, pth, g_Pt_h);   SYM(bf16, ptl, g_Pt_l);
    SYM(bf16, w1h, g_W1_h);   SYM(bf16, w1l, g_W1_l);
    SYM(bf16, w2h, g_W2_h);   SYM(bf16, w2l, g_W2_l);
    SYM(float, c1p, g_c1);    SYM(float, c2p, g_c2);

    // raise dynamic smem limit for all mm instantiations
    cudaFuncSetAttribute(mm_kernel<false, true, false, true, false, false>,
                         cudaFuncAttributeMaxDynamicSharedMemorySize, MM_SMEM);
    cudaFuncSetAttribute(mm_kernel<false, true, false, true, false, true>,
                         cudaFuncAttributeMaxDynamicSharedMemorySize, MM_SMEM);
    cudaFuncSetAttribute(mm_kernel<true, true, false, false, true, false>,
                         cudaFuncAttributeMaxDynamicSharedMemorySize, MM_SMEM);
    cudaFuncSetAttribute(mm_kernel<false, true, true, true, false, true>,
                         cudaFuncAttributeMaxDynamicSharedMemorySize, MM_SMEM);

    // ---- weight precompute (independent of activations)
    mt_kernel<<<1024, 256>>>(Wq, bq, Wk);
    pt_kernel<<<256, 256>>>(Wv, Wf);
    c2_kernel<<<1, 256>>>(bv, Wf, bf_);
    w12_cvt_kernel<<<2048, 256>>>(W1, W2);
    center_cvt_kernel<<<S_TOTAL, 256>>>(x);

    // G1: qk = Xc @ Mt^T + c1           (M=5120, N=1024, K=256) -> fp32
    mm_kernel<false, true, false, true, false, false><<<dim3(16, 40), 256, MM_SMEM>>>(
        xch, xcl, 256, mth, mtl, 256,
        qkp, nullptr, nullptr, 1024, c1p, nullptr, 0, 256);

    // fused scores/softmax/weighted-avg -> xbar bf16 split
    attn_kernel<<<S_TOTAL, 256>>>(x, qkp);

    // G2: att = xbar @ Pt^T + c2        (M=5120, N=256, K=1024) -> fp32 + stats
    mm_kernel<false, true, false, true, false, true><<<dim3(4, 40), 256, MM_SMEM>>>(
        xbh, xbl, 1024, pth, ptl, 1024,
        attp, nullptr, nullptr, 256, c2p, nullptr, 0, 1024);

    // LayerNorm1
    finalize_kernel<<<1, 32>>>();
    ln_apply_kernel<<<S_TOTAL, 256>>>(attp, ln1w, ln1b, o1p, o1h, o1l);

    // G3: h1 = relu(out1 @ W1^T + b1)   (N=1024, K=256) -> bf16 split
    mm_kernel<true, true, false, false, true, false><<<dim3(16, 40), 256, MM_SMEM>>>(
        o1h, o1l, 256, w1h, w1l, 256,
        nullptr, h1h, h1l, 1024, b1, nullptr, 0, 256);

    // G4: y = h1 @ W2^T + b2 + out1     (N=256, K=1024) -> fp32 + stats
    mm_kernel<false, true, true, true, false, true><<<dim3(4, 40), 256, MM_SMEM>>>(
        h1h, h1l, 1024, w2h, w2l, 1024,
        yp, nullptr, nullptr, 256, b2, o1p, 256, 1024);

    // LayerNorm2 -> out
    finalize_kernel<<<1, 32>>>();
    ln_apply_kernel<<<S_TOTAL, 256>>>(yp, ln2w, ln2b, out, nullptr, nullptr);
}

// round 9
// speedup vs baseline: 1.4419x; 1.4419x over previous
#include <cuda_runtime.h>
#include <cuda_fp16.h>
#include <mma.h>
#include <cstdint>
#include <cstddef>

using namespace nvcuda;

#define S_TOTAL     5120
#define EPSLN       1e-5f
#define BATCH_ELEMS 327680

// ===================== scratch (static __device__) ==========================
__device__ float g_qk  [S_TOTAL * 1024];
__device__ float g_att [S_TOTAL * 256];
__device__ float g_out1[S_TOTAL * 256];
__device__ float g_y   [S_TOTAL * 256];

__device__ __align__(16) __half g_xc[S_TOTAL * 256];
__device__ __align__(16) __half g_xb[S_TOTAL * 1024];
__device__ __align__(16) __half g_o1[S_TOTAL * 256];
__device__ __align__(16) __half g_h1[S_TOTAL * 1024];

__device__ __align__(16) __half g_Mt[262144];   // (1024, 256)  folded q/k weights
__device__ __align__(16) __half g_Pt[262144];   // (256, 1024)  folded v/f weights
__device__ __align__(16) __half g_W1[262144];
__device__ __align__(16) __half g_W2[262144];
__device__ float g_c1[1024];
__device__ float g_c2[256];

__device__ float2 g_part[320];
__device__ float g_mu[4];
__device__ float g_rsd[4];

// ===================== helpers ==============================================
__device__ __forceinline__ uint32_t smem_u32(const void* p) {
    uint32_t a;
    asm("{ .reg .u64 t; cvta.to.shared.u64 t, %1; cvt.u32.u64 %0, t; }" : "=r"(a) : "l"(p));
    return a;
}
__device__ __forceinline__ void cp16(void* dst, const void* src) {
    asm volatile("cp.async.cg.shared.global [%0], [%1], 16;" ::
                 "r"(smem_u32(dst)), "l"(src));
}
#define CP_COMMIT()  asm volatile("cp.async.commit_group;" ::: "memory")
#define CP_WAIT(n)   asm volatile("cp.async.wait_group %0;" :: "n"(n) : "memory")

// ===================== weight precompute ====================================
// Mt[n=h*256+fo][fi] = 0.125 * sum_d Wq[(h*64+d)*256+fi] * Wk[(h*64+d)*256+fo]
// c1[n]            = 0.125 * sum_d bq[h*64+d] * Wk[(h*64+d)*256+fo]
__global__ void mt_kernel(const float* __restrict__ Wq, const float* __restrict__ bq,
                          const float* __restrict__ Wk) {
    __shared__ float wk_s[64];
    const int n = blockIdx.x, h = n >> 8, fo = n & 255;
    const int tid = threadIdx.x;
    if (tid < 64) wk_s[tid] = Wk[(h * 64 + tid) * 256 + fo];
    __syncthreads();
    float acc = 0.f;
#pragma unroll 8
    for (int d = 0; d < 64; d++)
        acc += Wq[(h * 64 + d) * 256 + tid] * wk_s[d];
    g_Mt[(size_t)n * 256 + tid] = __float2half(0.125f * acc);
    if (tid == 0) {
        float c = 0.f;
        for (int d = 0; d < 64; d++) c += bq[h * 64 + d] * wk_s[d];
        g_c1[n] = 0.125f * c;
    }
}

// Pt[o][h*256+f] = sum_d Wv[(h*64+d)*256+f] * Wf[o*256 + h*64+d]
__global__ void pt_kernel(const float* __restrict__ Wv, const float* __restrict__ Wf) {
    __shared__ float wf_s[1024];
    const int o = blockIdx.x, tid = threadIdx.x;
#pragma unroll
    for (int j = 0; j < 4; j++) wf_s[j * 256 + tid] = Wf[o * 256 + j * 256 + tid];
    __syncthreads();
#pragma unroll
    for (int h = 0; h < 4; h++) {
        float acc = 0.f;
#pragma unroll 8
        for (int d = 0; d < 64; d++)
            acc += Wv[(h * 64 + d) * 256 + tid] * wf_s[h * 64 + d];
        g_Pt[(size_t)o * 1024 + h * 256 + tid] = __float2half(acc);
    }
}

// c2[o] = sum_hd bv[hd]*Wf[o*256+hd] + bf[o]
__global__ void c2_kernel(const float* __restrict__ bv, const float* __restrict__ Wf,
                          const float* __restrict__ bff) {
    __shared__ float bv_s[256];
    const int o = threadIdx.x;
    bv_s[o] = bv[o];
    __syncthreads();
    float acc = bff[o];
    for (int j = 0; j < 256; j++) acc += bv_s[j] * Wf[o * 256 + j];
    g_c2[o] = acc;
}

// W1 + W2 convert (524288 elems)
__global__ void w12_cvt_kernel(const float* __restrict__ W1, const float* __restrict__ W2) {
    int i = blockIdx.x * 256 + threadIdx.x;
    if (i < 262144) g_W1[i] = __float2half(W1[i]);
    else            g_W2[i - 262144] = __float2half(W2[i - 262144]);
}

// gather patch-center rows of x -> fp16
__global__ void center_cvt_kernel(const float* __restrict__ x) {
    int s = blockIdx.x, f = threadIdx.x;
    g_xc[(size_t)s * 256 + f] = __float2half(x[(size_t)s * 6400 + 3072 + f]);
}

// ===================== pipelined fp16 wmma GEMM =============================
// C[m,n] = sum_k A[m,k]*B[n,k]; BM=BN=64, BK=32, 128 thr (4 warps), 3-stage
#define LDT 40
#define B_OFF (64 * LDT)
#define STAGE (128 * LDT)      // 5120 half = 10240 B per stage

template<bool RELU, bool BIAS, bool RES, bool WF32, bool WF16, bool STATS>
__global__ __launch_bounds__(128) void mm_kernel(
    const __half* __restrict__ A, int lda,
    const __half* __restrict__ B, int ldb,
    float* __restrict__ Cf, __half* __restrict__ Ch, int ldc,
    const float* __restrict__ bias,
    const float* __restrict__ Res, int ldr, int Ktot)
{
    __shared__ union {
        __half stg[3 * STAGE];       // 30720 B
        float cout[64 * 64];         // 16384 B (aliased after drain)
    } sm;
    __shared__ float rbuf[256];

    const int tid = threadIdx.x;
    const int wid = tid >> 5;
    const int wm = wid >> 1, wn = wid & 1;       // warp grid 2x2, tile 32x32
    const int m0 = blockIdx.y * 64, n0 = blockIdx.x * 64;

    const int lr = tid >> 1, lc = (tid & 1) * 16;   // loader: 64 rows x 2 chunks

    const int KT = Ktot >> 5;

    auto issue = [&](int s, int kt) {
        __half* st = sm.stg + s * STAGE;
        const int k0 = kt << 5;
        const __half* Ap = A + (size_t)(m0 + lr) * lda + k0 + lc;
        const __half* Bp = B + (size_t)(n0 + lr) * ldb + k0 + lc;
        cp16(st + lr * LDT + lc,             Ap);
        cp16(st + lr * LDT + lc + 8,         Ap + 8);
        cp16(st + B_OFF + lr * LDT + lc,     Bp);
        cp16(st + B_OFF + lr * LDT + lc + 8, Bp + 8);
    };

    wmma::fragment<wmma::accumulator, 16, 16, 16, float> cacc[2][2];
#pragma unroll
    for (int i = 0; i < 2; i++)
#pragma unroll
        for (int j = 0; j < 2; j++) wmma::fill_fragment(cacc[i][j], 0.0f);

    issue(0, 0); CP_COMMIT();
    issue(1, 1); CP_COMMIT();

    for (int kt = 0; kt < KT; kt++) {
        CP_WAIT(1);
        __syncthreads();
        const __half* st = sm.stg + (kt % 3) * STAGE;
#pragma unroll
        for (int ks = 0; ks < 32; ks += 16) {
            wmma::fragment<wmma::matrix_a, 16, 16, 16, __half, wmma::row_major> af[2];
            wmma::fragment<wmma::matrix_b, 16, 16, 16, __half, wmma::col_major> bfr[2];
#pragma unroll
            for (int i = 0; i < 2; i++)
                wmma::load_matrix_sync(af[i], st + (wm * 32 + i * 16) * LDT + ks, LDT);
#pragma unroll
            for (int j = 0; j < 2; j++)
                wmma::load_matrix_sync(bfr[j], st + B_OFF + (wn * 32 + j * 16) * LDT + ks, LDT);
#pragma unroll
            for (int i = 0; i < 2; i++)
#pragma unroll
                for (int j = 0; j < 2; j++)
                    wmma::mma_sync(cacc[i][j], af[i], bfr[j], cacc[i][j]);
        }
        __syncthreads();
        if (kt + 2 < KT) issue((kt + 2) % 3, kt + 2);
        CP_COMMIT();
    }
    CP_WAIT(0);
    __syncthreads();

#pragma unroll
    for (int i = 0; i < 2; i++)
#pragma unroll
        for (int j = 0; j < 2; j++)
            wmma::store_matrix_sync(
                sm.cout + (wm * 32 + i * 16) * 64 + wn * 32 + j * 16,
                cacc[i][j], 64, wmma::mem_row_major);
    __syncthreads();

    // postprocess: r = tid>>1 (64 rows), half-row of 32 floats each
    const int r = tid >> 1, ch = (tid & 1) * 32;
    const int m = m0 + r;
    float*  cf = WF32 ? (Cf + (size_t)m * ldc + n0 + ch) : nullptr;
    __half* c16 = WF16 ? (Ch + (size_t)m * ldc + n0 + ch) : nullptr;

    float lsum = 0.f, lss = 0.f;
#pragma unroll
    for (int q = 0; q < 8; q++) {
        float4 v = *(float4*)(sm.cout + r * 64 + ch + q * 4);
        if (BIAS) {
            const float4 b4 = *(const float4*)(bias + n0 + ch + q * 4);
            v.x += b4.x; v.y += b4.y; v.z += b4.z; v.w += b4.w;
        }
        if (RELU) {
            v.x = fmaxf(v.x, 0.f); v.y = fmaxf(v.y, 0.f);
            v.z = fmaxf(v.z, 0.f); v.w = fmaxf(v.w, 0.f);
        }
        if (RES) {
            const float4 r4 = *(const float4*)(Res + (size_t)m * ldr + n0 + ch + q * 4);
            v.x += r4.x; v.y += r4.y; v.z += r4.z; v.w += r4.w;
        }
        if (STATS) {
            lsum += v.x + v.y + v.z + v.w;
            lss  += v.x * v.x + v.y * v.y + v.z * v.z + v.w * v.w;
        }
        if (WF32) *(float4*)(cf + q * 4) = v;
        if (WF16) {
            __half2 p0; p0.x = __float2half(v.x); p0.y = __float2half(v.y);
            __half2 p1; p1.x = __float2half(v.z); p1.y = __float2half(v.w);
            *(__half2*)(c16 + q * 4)     = p0;
            *(__half2*)(c16 + q * 4 + 2) = p1;
        }
    }

    if (STATS) {
        rbuf[tid] = lsum;
        __syncthreads();
        for (int o = 64; o; o >>= 1) {
            if (tid < o) rbuf[tid] += rbuf[tid + o];
            __syncthreads();
        }
        float tsum = rbuf[0];
        __syncthreads();
        rbuf[tid] = lss;
        __syncthreads();
        for (int o = 64; o; o >>= 1) {
            if (tid < o) rbuf[tid] += rbuf[tid + o];
            __syncthreads();
        }
        if (tid == 0)
            g_part[blockIdx.y * gridDim.x + blockIdx.x] = make_float2(tsum, rbuf[0]);
    }
}

// ===================== fused attention (fp32, memory-bound) =================
__global__ void attn_kernel(const float* __restrict__ x,
                            const float* __restrict__ qk) {
    __shared__ float xs[6400];
    __shared__ float qs[1024];
    __shared__ float scr[128];
    __shared__ float wts[128];

    const int s = blockIdx.x;
    const int tid = threadIdx.x;

    const float4* xg = (const float4*)(x + (size_t)s * 6400);
    for (int i = tid; i < 1600; i += 256) ((float4*)xs)[i] = xg[i];
    ((float4*)qs)[tid] = ((const float4*)(qk + (size_t)s * 1024))[tid];
    __syncthreads();

    const int w = tid >> 5, l = tid & 31;
    for (int d = w; d < 100; d += 8) {
        const int h = d / 25, p = d % 25;
        const float* xp = xs + p * 256;
        const float* qh = qs + h * 256;
        float acc = 0.f;
#pragma unroll
        for (int f = l; f < 256; f += 32) acc += qh[f] * xp[f];
#pragma unroll
        for (int o = 16; o; o >>= 1) acc += __shfl_xor_sync(0xffffffffu, acc, o);
        if (l == 0) scr[d] = acc;              // 1/8 folded into Mt/c1
    }
    __syncthreads();

    if (tid < 4) {
        float mx = -1e30f;
        for (int p = 0; p < 25; p++) mx = fmaxf(mx, scr[tid * 25 + p]);
        float e[25], sum = 0.f;
        for (int p = 0; p < 25; p++) { e[p] = expf(scr[tid * 25 + p] - mx); sum += e[p]; }
        const float inv = 1.f / sum;
        for (int p = 0; p < 25; p++) wts[tid * 25 + p] = e[p] * inv;
    }
    __syncthreads();

    float acc[4] = {0.f, 0.f, 0.f, 0.f};
    for (int p = 0; p < 25; p++) {
        const float v = xs[p * 256 + tid];
#pragma unroll
        for (int h = 0; h < 4; h++) acc[h] += wts[h * 25 + p] * v;
    }
#pragma unroll
    for (int h = 0; h < 4; h++)
        g_xb[(size_t)s * 1024 + h * 256 + tid] = __float2half(acc[h]);
}

// ===================== LayerNorm finalize + apply ===========================
__global__ void finalize_kernel() {
    const int b = threadIdx.x;
    if (b < 4) {
        float s = 0.f, ss = 0.f;
        for (int y = b * 20; y < b * 20 + 20; y++)
            for (int xg = 0; xg < 4; xg++) {
                const float2 v = g_part[y * 4 + xg];
                s += v.x; ss += v.y;
            }
        const float mu = s / (float)BATCH_ELEMS;
        const float var = ss / (float)BATCH_ELEMS - mu * mu;
        g_mu[b] = mu;
        g_rsd[b] = rsqrtf(var + EPSLN);
    }
}

__global__ void ln_apply_kernel(const float* __restrict__ src,
                                const float* __restrict__ w,
                                const float* __restrict__ bb,
                                float* __restrict__ dst,
                                __half* __restrict__ dh) {
    const int i = blockIdx.x * 256 + threadIdx.x;
    const int b = i / BATCH_ELEMS;
    const int r = i - b * BATCH_ELEMS;
    const float v = (src[i] - g_mu[b]) * g_rsd[b] * w[r] + bb[r];
    dst[i] = v;
    if (dh) dh[i] = __float2half(v);
}

// ===================== launch ===============================================
#define SYM(T, p, s) T* p; { void* t_; cudaGetSymbolAddress(&t_, s); p = (T*)t_; }

extern "C" void kernel_launch(void* const* d_in, const int* in_sizes, int n_in,
                              void* d_out, int out_size) {
    const float* x    = (const float*)d_in[0];
    const float* Wq   = (const float*)d_in[1];
    const float* bq   = (const float*)d_in[2];
    const float* Wk   = (const float*)d_in[3];
    // bk (d_in[4]) irrelevant: constant shift under softmax
    const float* Wv   = (const float*)d_in[5];
    const float* bv   = (const float*)d_in[6];
    const float* Wf   = (const float*)d_in[7];
    const float* bf_  = (const float*)d_in[8];
    const float* ln1w = (const float*)d_in[9];
    const float* ln1b = (const float*)d_in[10];
    const float* ln2w = (const float*)d_in[11];
    const float* ln2b = (const float*)d_in[12];
    const float* W1   = (const float*)d_in[13];
    const float* b1   = (const float*)d_in[14];
    const float* W2   = (const float*)d_in[15];
    const float* b2   = (const float*)d_in[16];
    float* out = (float*)d_out;

    SYM(float, qkp,  g_qk);   SYM(float, attp, g_att);
    SYM(float, o1p,  g_out1); SYM(float, yp,   g_y);
    SYM(__half, xcp, g_xc);   SYM(__half, xbp, g_xb);
    SYM(__half, o1hp, g_o1);  SYM(__half, h1p, g_h1);
    SYM(__half, mtp, g_Mt);   SYM(__half, ptp, g_Pt);
    SYM(__half, w1p, g_W1);   SYM(__half, w2p, g_W2);
    SYM(float, c1p, g_c1);    SYM(float, c2p, g_c2);

    // ---- weight precompute (independent of activations)
    mt_kernel<<<1024, 256>>>(Wq, bq, Wk);
    pt_kernel<<<256, 256>>>(Wv, Wf);
    c2_kernel<<<1, 256>>>(bv, Wf, bf_);
    w12_cvt_kernel<<<2048, 256>>>(W1, W2);
    center_cvt_kernel<<<S_TOTAL, 256>>>(x);

    // G1: qk = Xc @ Mt^T + c1          (M=5120, N=1024, K=256) -> fp32
    mm_kernel<false, true, false, true, false, false><<<dim3(16, 80), 128>>>(
        xcp, 256, mtp, 256, qkp, nullptr, 1024, c1p, nullptr, 0, 256);

    // fused scores/softmax/weighted-avg -> xbar fp16
    attn_kernel<<<S_TOTAL, 256>>>(x, qkp);

    // G2: att = xbar @ Pt^T + c2       (M=5120, N=256, K=1024) -> fp32 + stats
    mm_kernel<false, true, false, true, false, true><<<dim3(4, 80), 128>>>(
        xbp, 1024, ptp, 1024, attp, nullptr, 256, c2p, nullptr, 0, 1024);

    // LayerNorm1
    finalize_kernel<<<1, 32>>>();
    ln_apply_kernel<<<S_TOTAL, 256>>>(attp, ln1w, ln1b, o1p, o1hp);

    // G3: h1 = relu(out1 @ W1^T + b1)  (N=1024, K=256) -> fp16
    mm_kernel<true, true, false, false, true, false><<<dim3(16, 80), 128>>>(
        o1hp, 256, w1p, 256, nullptr, h1p, 1024, b1, nullptr, 0, 256);

    // G4: y = h1 @ W2^T + b2 + out1    (N=256, K=1024) -> fp32 + stats
    mm_kernel<false, true, true, true, false, true><<<dim3(4, 80), 128>>>(
        h1p, 1024, w2p, 1024, yp, nullptr, 256, b2, o1p, 256, 1024);

    // LayerNorm2 -> out
    finalize_kernel<<<1, 32>>>();
    ln_apply_kernel<<<S_TOTAL, 256>>>(yp, ln2w, ln2b, out, nullptr);
}